// round 15
// baseline (speedup 1.0000x reference)
#include <cuda_runtime.h>
#include <cuda_bf16.h>
#include <cstdint>
#include <math.h>

// ============================================================================
// ARDiscriminator on GB300 — round 14: R13 base (572.9us), one change:
// conv CTA tile 128x128 via 32-wide K slabs (32KB/stage, 3-stage pipeline,
// still 2 CTAs/SM). A traffic halved, MMA:ldsm 3.0 -> 4.0.
// wn path / prep / finalize byte-identical to R13.
// ============================================================================

#define NFRAMES 2048

template <int N> struct ILog2 { static constexpr int v = 1 + ILog2<N / 2>::v; };
template <> struct ILog2<1> { static constexpr int v = 0; };

// ---------------- static scratch -------------------------------------------
__device__ __align__(128) __nv_bfloat16 g_pAhi[(size_t)NFRAMES * 128 * 128];
__device__ __align__(128) __nv_bfloat16 g_pAlo[(size_t)NFRAMES * 128 * 128];
__device__ __align__(128) __nv_bfloat16 g_pBhi[(size_t)NFRAMES * 64 * 128];
__device__ __align__(128) __nv_bfloat16 g_pBlo[(size_t)NFRAMES * 64 * 128];
__device__ __align__(128) float         g_H  [2][NFRAMES * 256];
__device__ __align__(128) __nv_bfloat16 g_Hhi[2][NFRAMES * 256];
__device__ __align__(128) __nv_bfloat16 g_Hlo[2][NFRAMES * 256];
__device__ __align__(128) float         g_pre [2 * 1024 * 256];
__device__ __align__(128) float         g_Henc[2048];
__device__ __align__(128) __nv_bfloat16 g_w123hi [3 * 128 * 896];
__device__ __align__(128) __nv_bfloat16 g_w123lo [3 * 128 * 896];
__device__ __align__(128) __nv_bfloat16 g_w4567hi[4 * 128 * 384];
__device__ __align__(128) __nv_bfloat16 g_w4567lo[4 * 128 * 384];
__device__ __align__(128) __nv_bfloat16 g_w8hi   [256 * 128];
__device__ __align__(128) __nv_bfloat16 g_w8lo   [256 * 128];
__device__ __align__(128) __nv_bfloat16 g_wnhi   [8 * 2 * 256 * 512];
__device__ __align__(128) __nv_bfloat16 g_wnlo   [8 * 2 * 256 * 512];

// ---------------- low-level helpers ----------------------------------------
__device__ __forceinline__ uint32_t smem_u32(const void* p) {
    uint32_t a;
    asm("{ .reg .u64 t; cvta.to.shared.u64 t, %1; cvt.u32.u64 %0, t; }"
        : "=r"(a) : "l"(p));
    return a;
}
__device__ __forceinline__ void cp16(uint32_t dst, const void* src, int sz) {
    asm volatile("cp.async.cg.shared.global [%0], [%1], 16, %2;"
                 :: "r"(dst), "l"(src), "r"(sz));
}
#define CP_COMMIT() asm volatile("cp.async.commit_group;")
#define CP_WAIT(n)  asm volatile("cp.async.wait_group %0;" :: "n"(n))

__device__ __forceinline__ void ldsm_x4(uint32_t (&r)[4], uint32_t addr) {
    asm volatile("ldmatrix.sync.aligned.m8n8.x4.shared.b16 {%0,%1,%2,%3}, [%4];"
                 : "=r"(r[0]), "=r"(r[1]), "=r"(r[2]), "=r"(r[3]) : "r"(addr));
}
__device__ __forceinline__ void mma_bf16(float (&c)[4], const uint32_t (&a)[4],
                                         uint32_t b0, uint32_t b1) {
    asm volatile(
        "mma.sync.aligned.m16n8k16.row.col.f32.bf16.bf16.f32 "
        "{%0,%1,%2,%3}, {%4,%5,%6,%7}, {%8,%9}, {%0,%1,%2,%3};"
        : "+f"(c[0]), "+f"(c[1]), "+f"(c[2]), "+f"(c[3])
        : "r"(a[0]), "r"(a[1]), "r"(a[2]), "r"(a[3]), "r"(b0), "r"(b1));
}

__device__ __forceinline__ int sw128(int off) { return off ^ ((off >> 3) & 0x70); }
__device__ __forceinline__ int sw64(int off)  { return off ^ ((off >> 3) & 0x30); }

__device__ __forceinline__ void split1(float v, __nv_bfloat16& h, __nv_bfloat16& l) {
    h = __float2bfloat16(v);
    l = __float2bfloat16(v - __bfloat162float(h));
}

// ---- wn pipeline buffer layout (128B rows, identical to R13) ---------------
static constexpr int SM_A_HI = 0;
static constexpr int SM_A_LO = 16384;
static constexpr int SM_B_HI = 32768;
static constexpr int SM_B_LO = 40960;
static constexpr int BUFSZ   = 49152;
static constexpr int SMEM_PIPE = 2 * BUFSZ;  // 96KB dynamic
// ---- conv pipeline buffer layout (64B rows, 32-wide K slabs) ---------------
static constexpr int CA_HI = 0;
static constexpr int CA_LO = 8192;
static constexpr int CB_HI = 16384;
static constexpr int CB_LO = 24576;
static constexpr int CV_BUF  = 32768;
static constexpr int CV_SMEM = 3 * CV_BUF;   // 96KB dynamic, 2 CTAs/SM

// ---- wn compute: 16-wide K chunk, warp tile 32M x 32N (128B rows) ----------
__device__ __forceinline__ void compute_kc(uint32_t base, int lane, int wm, int wn_,
                                           int kc, float (&c)[2][4][4]) {
    uint32_t bh[4][2], bl[4][2];
#pragma unroll
    for (int pr = 0; pr < 2; pr++) {
        int off = (wn_ + pr * 16 + ((lane >> 4) & 1) * 8 + (lane & 7)) * 128 +
                  (kc + ((lane >> 3) & 1) * 8) * 2;
        int swo = sw128(off);
        uint32_t th[4], tl[4];
        ldsm_x4(th, base + SM_B_HI + swo);
        ldsm_x4(tl, base + SM_B_LO + swo);
        bh[pr * 2][0] = th[0]; bh[pr * 2][1] = th[1];
        bh[pr * 2 + 1][0] = th[2]; bh[pr * 2 + 1][1] = th[3];
        bl[pr * 2][0] = tl[0]; bl[pr * 2][1] = tl[1];
        bl[pr * 2 + 1][0] = tl[2]; bl[pr * 2 + 1][1] = tl[3];
    }
#pragma unroll
    for (int mi = 0; mi < 2; mi++) {
        int off = (wm + mi * 16 + (lane & 7) + ((lane >> 3) & 1) * 8) * 128 +
                  (kc + (lane >> 4) * 8) * 2;
        int swo = sw128(off);
        uint32_t ah[4], al[4];
        ldsm_x4(ah, base + SM_A_HI + swo);
        ldsm_x4(al, base + SM_A_LO + swo);
#pragma unroll
        for (int ni = 0; ni < 4; ni++) {
            mma_bf16(c[mi][ni], ah, bh[ni][0], bh[ni][1]);
            mma_bf16(c[mi][ni], ah, bl[ni][0], bl[ni][1]);
            mma_bf16(c[mi][ni], al, bh[ni][0], bh[ni][1]);
        }
    }
}

// ---- conv compute: 16-wide K chunk, warp tile 32M x 64N (64B rows) ---------
// A frags resident; B streamed per 16-col pair to cap live registers.
__device__ __forceinline__ void compute_c128(uint32_t base, int lane, int wm, int wn_,
                                             int kc, float (&c)[2][8][4]) {
    uint32_t ah[2][4], al[2][4];
#pragma unroll
    for (int mi = 0; mi < 2; mi++) {
        int off = (wm + mi * 16 + (lane & 7) + ((lane >> 3) & 1) * 8) * 64 +
                  (kc + (lane >> 4) * 8) * 2;
        int swo = sw64(off);
        ldsm_x4(ah[mi], base + CA_HI + swo);
        ldsm_x4(al[mi], base + CA_LO + swo);
    }
#pragma unroll
    for (int pr = 0; pr < 4; pr++) {
        int off = (wn_ + pr * 16 + ((lane >> 4) & 1) * 8 + (lane & 7)) * 64 +
                  (kc + ((lane >> 3) & 1) * 8) * 2;
        int swo = sw64(off);
        uint32_t th[4], tl[4];
        ldsm_x4(th, base + CB_HI + swo);
        ldsm_x4(tl, base + CB_LO + swo);
#pragma unroll
        for (int mi = 0; mi < 2; mi++) {
            mma_bf16(c[mi][pr * 2],     ah[mi], th[0], th[1]);
            mma_bf16(c[mi][pr * 2],     ah[mi], tl[0], tl[1]);
            mma_bf16(c[mi][pr * 2],     al[mi], th[0], th[1]);
            mma_bf16(c[mi][pr * 2 + 1], ah[mi], th[2], th[3]);
            mma_bf16(c[mi][pr * 2 + 1], ah[mi], tl[2], tl[3]);
            mma_bf16(c[mi][pr * 2 + 1], al[mi], th[2], th[3]);
        }
    }
}

// ---------------- merged prep_weights + conv0 (identical to R13) ------------
__global__ void prep_and_conv0(const float* __restrict__ x,
                               const float* __restrict__ w0,
                               const float* __restrict__ w123,
                               const float* __restrict__ w4567,
                               const float* __restrict__ w8,
                               const float* __restrict__ wm,
                               const float* __restrict__ wg) {
    const int tid = threadIdx.x;
    if (blockIdx.x < NFRAMES) {
        __shared__ float xin[256];
        __shared__ float w0s[896];
        const int f = blockIdx.x;
        const int b = f >> 8, t = (f & 255) + 256;
        xin[tid] = x[(b * 256 + tid) * 512 + t];
        for (int i = tid; i < 896; i += 256) w0s[i] = w0[i];
        __syncthreads();
        const int co = tid & 127;
        const int ph = tid >> 7;
#pragma unroll 4
        for (int u = 0; u < 64; u++) {
            int p = ph * 64 + u;
            float s = 0.f;
#pragma unroll
            for (int k = 0; k < 7; k++) {
                int ip = 2 * p + k - 3;
                float xv = (ip >= 0 && ip < 256) ? xin[ip] : 0.f;
                s = fmaf(w0s[co * 7 + k], xv, s);
            }
            s = s > 0.f ? s : 0.2f * s;
            size_t o = ((size_t)f * 128 + p) * 128 + co;
            split1(s, g_pAhi[o], g_pAlo[o]);
        }
        return;
    }
    const int stride = 512 * 256;
    const int t0 = (blockIdx.x - NFRAMES) * 256 + tid;
    for (int e = t0; e < 3 * 128 * 896; e += stride) {
        int l = e / (128 * 896), r = e % (128 * 896);
        int co = r / 896, k = r % 896;
        int kw = k >> 7, ci = k & 127;
        split1(w123[((l * 128 + co) * 128 + ci) * 7 + kw], g_w123hi[e], g_w123lo[e]);
    }
    for (int e = t0; e < 4 * 128 * 384; e += stride) {
        int l = e / (128 * 384), r = e % (128 * 384);
        int co = r / 384, k = r % 384;
        int kw = k >> 7, ci = k & 127;
        split1(w4567[((l * 128 + co) * 128 + ci) * 3 + kw], g_w4567hi[e], g_w4567lo[e]);
    }
    for (int e = t0; e < 256 * 128; e += stride) {
        int co = e >> 7, ci = e & 127;
        split1(w8[co * 128 + ci], g_w8hi[e], g_w8lo[e]);
    }
    for (int e = t0; e < 8 * 2 * 256 * 512; e += stride) {
        int lz = e / (256 * 512), r = e % (256 * 512);
        int co = r / 512, k = r % 512;
        int tap = k >> 8, ci = k & 255;
        int l = lz >> 1, z = lz & 1;
        const float* w = z ? wg : wm;
        split1(w[((l * 256 + co) * 256 + ci) * 2 + tap], g_wnhi[e], g_wnlo[e]);
    }
}

// ---------------- conv-as-GEMM: 128x128 tile, 32-wide slabs, 3 stages -------
template <int KW, int PAD, int LIN, int LOUT, bool RELU, bool LAST>
__global__ __launch_bounds__(256, 2)
void conv_mma3(const __nv_bfloat16* __restrict__ in_hi,
               const __nv_bfloat16* __restrict__ in_lo,
               const __nv_bfloat16* __restrict__ w_hi,
               const __nv_bfloat16* __restrict__ w_lo,
               __nv_bfloat16* __restrict__ out_hi,
               __nv_bfloat16* __restrict__ out_lo) {
    constexpr int K = KW * 128;
    constexpr int NST = K / 32;          // >= 4 always
    constexpr int LOG = ILog2<LOUT>::v;
    extern __shared__ __align__(1024) char smem[];
    const uint32_t sb = smem_u32(smem);

    const int tid = threadIdx.x;
    const int lane = tid & 31;
    const int warp = tid >> 5;
    const int wm = (warp >> 1) * 32;
    const int wn_ = (warp & 1) * 64;
    const int col0 = blockIdx.x * 128;
    const int m0 = blockIdx.y * 128;

    float c[2][8][4];
#pragma unroll
    for (int i = 0; i < 2; i++)
#pragma unroll
        for (int j = 0; j < 8; j++)
#pragma unroll
            for (int k = 0; k < 4; k++) c[i][j][k] = 0.f;

    auto issue = [&](int s) {
        const uint32_t bo = sb + (s % 3) * CV_BUF;
        const int kw = s >> 2;
        const int ci0 = (s & 3) * 32;
        // A: 128 rows x 64B, 512 slots/plane
#pragma unroll
        for (int g = 0; g < 2; g++) {
            int gi = tid + g * 256;
            int row = gi >> 2, j = gi & 3;
            uint32_t off = sw64(row * 64 + j * 16);
            size_t so = (size_t)(m0 + row) * K + s * 32 + j * 8;
            cp16(bo + CA_HI + off, w_hi + so, 16);
            cp16(bo + CA_LO + off, w_lo + so, 16);
        }
        // B: 128 rows x 64B (im2col), 512 slots/plane
#pragma unroll
        for (int g = 0; g < 2; g++) {
            int gi = tid + g * 256;
            int row = gi >> 2, j = gi & 3;
            int col = col0 + row;
            int f = col >> LOG;
            int p = col & (LOUT - 1);
            int ip = 2 * p + kw - PAD;
            bool v = ((unsigned)ip < (unsigned)LIN);
            size_t so = ((size_t)f * LIN + (v ? ip : 0)) * 128 + ci0 + j * 8;
            int sz = v ? 16 : 0;
            uint32_t off = sw64(row * 64 + j * 16);
            cp16(bo + CB_HI + off, in_hi + so, sz);
            cp16(bo + CB_LO + off, in_lo + so, sz);
        }
    };

    issue(0); CP_COMMIT();
    issue(1); CP_COMMIT();
    for (int s = 0; s < NST; s++) {
        if (s < NST - 1) { CP_WAIT(1); } else { CP_WAIT(0); }
        __syncthreads();
        const uint32_t base = sb + (s % 3) * CV_BUF;
        compute_c128(base, lane, wm, wn_, 0, c);
        if (s + 2 < NST) { issue(s + 2); CP_COMMIT(); }
        compute_c128(base, lane, wm, wn_, 16, c);
    }

#pragma unroll
    for (int mi = 0; mi < 2; mi++) {
#pragma unroll
        for (int ni = 0; ni < 8; ni++) {
            int r0 = wm + mi * 16 + (lane >> 2);
            int colb = col0 + wn_ + ni * 8 + (lane & 3) * 2;
#pragma unroll
            for (int e = 0; e < 4; e++) {
                int row = r0 + (e >> 1) * 8;
                int col = colb + (e & 1);
                float xv = c[mi][ni][e];
                if (RELU) xv = xv > 0.f ? xv : 0.2f * xv;
                if (LAST) {
                    size_t o = (size_t)col * 256 + m0 + row;
                    g_H[0][o] = xv;
                    split1(xv, g_Hhi[0][o], g_Hlo[0][o]);
                    if ((col & 255) == 255)
                        g_Henc[(col >> 8) * 256 + m0 + row] = xv;
                } else {
                    size_t o = (size_t)col * 128 + row;
                    split1(xv, out_hi[o], out_lo[o]);
                }
            }
        }
    }
}

// ---------------- WaveNet GEMM (main+gate), sparse cone columns (R13) -------
__global__ __launch_bounds__(256, 2)
void wn_mma2(int layer, int ncols) {
    extern __shared__ __align__(1024) char smem[];
    const uint32_t sb = smem_u32(smem);

    const int tid = threadIdx.x;
    const int lane = tid & 31;
    const int warp = tid >> 5;
    const int wm = (warp >> 1) * 32;
    const int wn_ = (warp & 1) * 32;
    const int col0 = blockIdx.x * 64;
    const int z = blockIdx.y >> 1;
    const int mh = blockIdx.y & 1;
    const int rd = layer & 1;
    const int dil = 1 << layer;
    const int ls = layer + 1;
    const int lperb = 7 - layer;
    const __nv_bfloat16* w_hi = g_wnhi + ((size_t)(layer * 2 + z) * 256 + mh * 128) * 512;
    const __nv_bfloat16* w_lo = g_wnlo + ((size_t)(layer * 2 + z) * 256 + mh * 128) * 512;
    const __nv_bfloat16* Hhi = g_Hhi[rd];
    const __nv_bfloat16* Hlo = g_Hlo[rd];

    float c[2][4][4];
#pragma unroll
    for (int i = 0; i < 2; i++)
#pragma unroll
        for (int j = 0; j < 4; j++)
#pragma unroll
            for (int k = 0; k < 4; k++) c[i][j][k] = 0.f;

    auto issue = [&](int s) {
        const uint32_t bo = sb + (s & 1) * BUFSZ;
        const int tap = s >> 2;
        const int ci0 = (s & 3) * 64;
#pragma unroll
        for (int g = 0; g < 4; g++) {
            int gi = tid + g * 256;
            int row = gi >> 3, j = gi & 7;
            uint32_t off = row * 128 + ((j ^ (row & 7)) << 4);
            size_t so = (size_t)row * 512 + s * 64 + j * 8;
            cp16(bo + SM_A_HI + off, w_hi + so, 16);
            cp16(bo + SM_A_LO + off, w_lo + so, 16);
        }
#pragma unroll
        for (int g = 0; g < 2; g++) {
            int gi = tid + g * 256;
            int row = gi >> 3, j = gi & 7;
            int colc = col0 + row;
            bool valid = colc < ncols;
            int cc = valid ? colc : 0;
            int b = cc >> lperb;
            int j2 = cc & ((1 << lperb) - 1);
            int tt = (j2 << ls) + (1 << ls) - 1;
            int scol = b * 256 + tt - (tap ? 0 : dil);
            size_t so = (size_t)scol * 256 + ci0 + j * 8;
            int sz = valid ? 16 : 0;
            uint32_t off = row * 128 + ((j ^ (row & 7)) << 4);
            cp16(bo + SM_B_HI + off, Hhi + so, sz);
            cp16(bo + SM_B_LO + off, Hlo + so, sz);
        }
    };

    issue(0); CP_COMMIT();
    for (int s = 0; s < 8; s++) {
        CP_WAIT(0);
        __syncthreads();
        const uint32_t base = sb + (s & 1) * BUFSZ;
        compute_kc(base, lane, wm, wn_, 0, c);
        if (s + 1 < 8) { issue(s + 1); CP_COMMIT(); }
        compute_kc(base, lane, wm, wn_, 16, c);
        compute_kc(base, lane, wm, wn_, 32, c);
        compute_kc(base, lane, wm, wn_, 48, c);
    }

    float* pre = g_pre + (size_t)z * 1024 * 256;
#pragma unroll
    for (int mi = 0; mi < 2; mi++) {
#pragma unroll
        for (int ni = 0; ni < 4; ni++) {
            int r0 = mh * 128 + wm + mi * 16 + (lane >> 2);
            int colb = col0 + wn_ + ni * 8 + (lane & 3) * 2;
#pragma unroll
            for (int e = 0; e < 4; e++) {
                int row = r0 + (e >> 1) * 8;
                int col = colb + (e & 1);
                if (col < ncols) pre[(size_t)col * 256 + row] = c[mi][ni][e];
            }
        }
    }
}

// ---------------- WaveNet pointwise: sparse cols, ping-pong H (R13) ----------
__global__ void wn_pointwise(int layer) {
    const int col = blockIdx.x;
    const int co = threadIdx.x;
    const int rd = layer & 1;
    const int ls = layer + 1;
    const int lperb = 7 - layer;
    int b = col >> lperb;
    int j2 = col & ((1 << lperb) - 1);
    int tt = (j2 << ls) + (1 << ls) - 1;
    size_t gidx = ((size_t)(b * 256 + tt)) * 256 + co;
    size_t pidx = (size_t)col * 256 + co;
    float pm = g_pre[pidx];
    float pg = g_pre[(size_t)1024 * 256 + pidx];
    float zv = tanhf(pm) * (1.f / (1.f + expf(-pg)));
    float h = g_H[rd][gidx] + zv;
    g_H[rd ^ 1][gidx] = h;
    split1(h, g_Hhi[rd ^ 1][gidx], g_Hlo[rd ^ 1][gidx]);
}

// ---------------- finalize ---------------------------------------------------
__global__ void finalize_kernel(const float* __restrict__ jw,
                                float* __restrict__ out, int out_size) {
    __shared__ float red[256];
    const int b = blockIdx.x;
    const int t = threadIdx.x;
    float v = g_H[0][((size_t)b * 256 + 255) * 256 + t] - g_Henc[b * 256 + t];
    out[b * 256 + t] = v;
    red[t] = v * jw[t];
    __syncthreads();
#pragma unroll
    for (int s = 128; s > 0; s >>= 1) {
        if (t < s) red[t] += red[t + s];
        __syncthreads();
    }
    if (t == 0 && out_size >= 2048 + 8) out[2048 + b] = red[0];
}

// ---------------- launch -----------------------------------------------------
extern "C" void kernel_launch(void* const* d_in, const int* in_sizes, int n_in,
                              void* d_out, int out_size) {
    const float* x     = (const float*)d_in[0];
    const float* w0    = (const float*)d_in[1];
    const float* w123  = (const float*)d_in[2];
    const float* w4567 = (const float*)d_in[3];
    const float* w8    = (const float*)d_in[4];
    const float* wm    = (const float*)d_in[5];
    const float* wg    = (const float*)d_in[6];
    const float* jw    = (const float*)d_in[7];
    float* out = (float*)d_out;

    __nv_bfloat16 *pAhi, *pAlo, *pBhi, *pBlo;
    __nv_bfloat16 *w123hi, *w123lo, *w4567hi, *w4567lo, *w8hi, *w8lo;
    cudaGetSymbolAddress((void**)&pAhi, g_pAhi);
    cudaGetSymbolAddress((void**)&pAlo, g_pAlo);
    cudaGetSymbolAddress((void**)&pBhi, g_pBhi);
    cudaGetSymbolAddress((void**)&pBlo, g_pBlo);
    cudaGetSymbolAddress((void**)&w123hi, g_w123hi);
    cudaGetSymbolAddress((void**)&w123lo, g_w123lo);
    cudaGetSymbolAddress((void**)&w4567hi, g_w4567hi);
    cudaGetSymbolAddress((void**)&w4567lo, g_w4567lo);
    cudaGetSymbolAddress((void**)&w8hi, g_w8hi);
    cudaGetSymbolAddress((void**)&w8lo, g_w8lo);

    cudaFuncSetAttribute(conv_mma3<7,3,128,64,true ,false>, cudaFuncAttributeMaxDynamicSharedMemorySize, CV_SMEM);
    cudaFuncSetAttribute(conv_mma3<7,3, 64,32,true ,false>, cudaFuncAttributeMaxDynamicSharedMemorySize, CV_SMEM);
    cudaFuncSetAttribute(conv_mma3<7,3, 32,16,true ,false>, cudaFuncAttributeMaxDynamicSharedMemorySize, CV_SMEM);
    cudaFuncSetAttribute(conv_mma3<3,1, 16, 8,true ,false>, cudaFuncAttributeMaxDynamicSharedMemorySize, CV_SMEM);
    cudaFuncSetAttribute(conv_mma3<3,1,  8, 4,true ,false>, cudaFuncAttributeMaxDynamicSharedMemorySize, CV_SMEM);
    cudaFuncSetAttribute(conv_mma3<3,1,  4, 2,true ,false>, cudaFuncAttributeMaxDynamicSharedMemorySize, CV_SMEM);
    cudaFuncSetAttribute(conv_mma3<3,1,  2, 1,true ,false>, cudaFuncAttributeMaxDynamicSharedMemorySize, CV_SMEM);
    cudaFuncSetAttribute(conv_mma3<1,0,  1, 1,false,true >, cudaFuncAttributeMaxDynamicSharedMemorySize, CV_SMEM);
    cudaFuncSetAttribute(wn_mma2, cudaFuncAttributeMaxDynamicSharedMemorySize, SMEM_PIPE);

    prep_and_conv0<<<NFRAMES + 512, 256>>>(x, w0, w123, w4567, w8, wm, wg);

    // (KW,PAD,LIN,LOUT,RELU,LAST); grid = (NFRAMES*LOUT/128, COUT/128)
    conv_mma3<7,3,128,64,true ,false><<<dim3(1024,1), 256, CV_SMEM>>>(pAhi, pAlo, w123hi,              w123lo,              pBhi, pBlo);
    conv_mma3<7,3, 64,32,true ,false><<<dim3( 512,1), 256, CV_SMEM>>>(pBhi, pBlo, w123hi + 1*128*896,  w123lo + 1*128*896,  pAhi, pAlo);
    conv_mma3<7,3, 32,16,true ,false><<<dim3( 256,1), 256, CV_SMEM>>>(pAhi, pAlo, w123hi + 2*128*896,  w123lo + 2*128*896,  pBhi, pBlo);
    conv_mma3<3,1, 16, 8,true ,false><<<dim3( 128,1), 256, CV_SMEM>>>(pBhi, pBlo, w4567hi,             w4567lo,             pAhi, pAlo);
    conv_mma3<3,1,  8, 4,true ,false><<<dim3(  64,1), 256, CV_SMEM>>>(pAhi, pAlo, w4567hi + 1*128*384, w4567lo + 1*128*384, pBhi, pBlo);
    conv_mma3<3,1,  4, 2,true ,false><<<dim3(  32,1), 256, CV_SMEM>>>(pBhi, pBlo, w4567hi + 2*128*384, w4567lo + 2*128*384, pAhi, pAlo);
    conv_mma3<3,1,  2, 1,true ,false><<<dim3(  16,1), 256, CV_SMEM>>>(pAhi, pAlo, w4567hi + 3*128*384, w4567lo + 3*128*384, pBhi, pBlo);
    conv_mma3<1,0,  1, 1,false,true ><<<dim3(  16,2), 256, CV_SMEM>>>(pBhi, pBlo, w8hi,                w8lo,                pAhi, pAlo);

    for (int l = 0; l < 8; l++) {
        int ncols = 8 * (256 >> (l + 1));            // 1024, 512, ..., 8
        int gx = (ncols + 63) / 64;
        wn_mma2<<<dim3(gx, 4), 256, SMEM_PIPE>>>(l, ncols);
        wn_pointwise<<<ncols, 256>>>(l);
    }

    finalize_kernel<<<8, 256>>>(jw, out, out_size);
}

// round 17
// speedup vs baseline: 1.0816x; 1.0816x over previous
#include <cuda_runtime.h>
#include <cuda_bf16.h>
#include <cstdint>
#include <math.h>

// ============================================================================
// ARDiscriminator on GB300 — round 16: R15 PDL design, API-name compile fix
// (programmaticStreamSerializationAllowed). Kernels byte-identical to R13.
// ============================================================================

#define NFRAMES 2048

template <int N> struct ILog2 { static constexpr int v = 1 + ILog2<N / 2>::v; };
template <> struct ILog2<1> { static constexpr int v = 0; };

#define PDL_WAIT()    asm volatile("griddepcontrol.wait;" ::: "memory")
#define PDL_TRIGGER() asm volatile("griddepcontrol.launch_dependents;")

// ---------------- static scratch -------------------------------------------
__device__ __align__(128) __nv_bfloat16 g_pAhi[(size_t)NFRAMES * 128 * 128];
__device__ __align__(128) __nv_bfloat16 g_pAlo[(size_t)NFRAMES * 128 * 128];
__device__ __align__(128) __nv_bfloat16 g_pBhi[(size_t)NFRAMES * 64 * 128];
__device__ __align__(128) __nv_bfloat16 g_pBlo[(size_t)NFRAMES * 64 * 128];
// ping-pong H buffers: layer l reads [l&1], writes [(l&1)^1]
__device__ __align__(128) float         g_H  [2][NFRAMES * 256];
__device__ __align__(128) __nv_bfloat16 g_Hhi[2][NFRAMES * 256];
__device__ __align__(128) __nv_bfloat16 g_Hlo[2][NFRAMES * 256];
__device__ __align__(128) float         g_pre [2 * 1024 * 256];
__device__ __align__(128) float         g_Henc[2048];
__device__ __align__(128) __nv_bfloat16 g_w123hi [3 * 128 * 896];
__device__ __align__(128) __nv_bfloat16 g_w123lo [3 * 128 * 896];
__device__ __align__(128) __nv_bfloat16 g_w4567hi[4 * 128 * 384];
__device__ __align__(128) __nv_bfloat16 g_w4567lo[4 * 128 * 384];
__device__ __align__(128) __nv_bfloat16 g_w8hi   [256 * 128];
__device__ __align__(128) __nv_bfloat16 g_w8lo   [256 * 128];
__device__ __align__(128) __nv_bfloat16 g_wnhi   [8 * 2 * 256 * 512];
__device__ __align__(128) __nv_bfloat16 g_wnlo   [8 * 2 * 256 * 512];

// ---------------- low-level helpers ----------------------------------------
__device__ __forceinline__ uint32_t smem_u32(const void* p) {
    uint32_t a;
    asm("{ .reg .u64 t; cvta.to.shared.u64 t, %1; cvt.u32.u64 %0, t; }"
        : "=r"(a) : "l"(p));
    return a;
}
__device__ __forceinline__ void cp16(uint32_t dst, const void* src, int sz) {
    asm volatile("cp.async.cg.shared.global [%0], [%1], 16, %2;"
                 :: "r"(dst), "l"(src), "r"(sz));
}
#define CP_COMMIT() asm volatile("cp.async.commit_group;")
#define CP_WAIT(n)  asm volatile("cp.async.wait_group %0;" :: "n"(n))

__device__ __forceinline__ void ldsm_x4(uint32_t (&r)[4], uint32_t addr) {
    asm volatile("ldmatrix.sync.aligned.m8n8.x4.shared.b16 {%0,%1,%2,%3}, [%4];"
                 : "=r"(r[0]), "=r"(r[1]), "=r"(r[2]), "=r"(r[3]) : "r"(addr));
}
__device__ __forceinline__ void mma_bf16(float (&c)[4], const uint32_t (&a)[4],
                                         uint32_t b0, uint32_t b1) {
    asm volatile(
        "mma.sync.aligned.m16n8k16.row.col.f32.bf16.bf16.f32 "
        "{%0,%1,%2,%3}, {%4,%5,%6,%7}, {%8,%9}, {%0,%1,%2,%3};"
        : "+f"(c[0]), "+f"(c[1]), "+f"(c[2]), "+f"(c[3])
        : "r"(a[0]), "r"(a[1]), "r"(a[2]), "r"(a[3]), "r"(b0), "r"(b1));
}

__device__ __forceinline__ int sw128(int off) { return off ^ ((off >> 3) & 0x70); }

__device__ __forceinline__ void split1(float v, __nv_bfloat16& h, __nv_bfloat16& l) {
    h = __float2bfloat16(v);
    l = __float2bfloat16(v - __bfloat162float(h));
}

// SMEM tile offsets within one pipeline buffer (identical to R13)
static constexpr int SM_A_HI = 0;
static constexpr int SM_A_LO = 16384;
static constexpr int SM_B_HI = 32768;
static constexpr int SM_B_LO = 40960;
static constexpr int BUFSZ   = 49152;
static constexpr int SMEM_PIPE = 2 * BUFSZ;  // 96KB dynamic

// one 16-wide K chunk of the 3-term split warp-tile compute (32M x 32N)
__device__ __forceinline__ void compute_kc(uint32_t base, int lane, int wm, int wn_,
                                           int kc, float (&c)[2][4][4]) {
    uint32_t bh[4][2], bl[4][2];
#pragma unroll
    for (int pr = 0; pr < 2; pr++) {
        int off = (wn_ + pr * 16 + ((lane >> 4) & 1) * 8 + (lane & 7)) * 128 +
                  (kc + ((lane >> 3) & 1) * 8) * 2;
        int swo = sw128(off);
        uint32_t th[4], tl[4];
        ldsm_x4(th, base + SM_B_HI + swo);
        ldsm_x4(tl, base + SM_B_LO + swo);
        bh[pr * 2][0] = th[0]; bh[pr * 2][1] = th[1];
        bh[pr * 2 + 1][0] = th[2]; bh[pr * 2 + 1][1] = th[3];
        bl[pr * 2][0] = tl[0]; bl[pr * 2][1] = tl[1];
        bl[pr * 2 + 1][0] = tl[2]; bl[pr * 2 + 1][1] = tl[3];
    }
#pragma unroll
    for (int mi = 0; mi < 2; mi++) {
        int off = (wm + mi * 16 + (lane & 7) + ((lane >> 3) & 1) * 8) * 128 +
                  (kc + (lane >> 4) * 8) * 2;
        int swo = sw128(off);
        uint32_t ah[4], al[4];
        ldsm_x4(ah, base + SM_A_HI + swo);
        ldsm_x4(al, base + SM_A_LO + swo);
#pragma unroll
        for (int ni = 0; ni < 4; ni++) {
            mma_bf16(c[mi][ni], ah, bh[ni][0], bh[ni][1]);
            mma_bf16(c[mi][ni], ah, bl[ni][0], bl[ni][1]);
            mma_bf16(c[mi][ni], al, bh[ni][0], bh[ni][1]);
        }
    }
}

// ---------------- merged prep_weights + conv0 (first node, no wait) ---------
__global__ void prep_and_conv0(const float* __restrict__ x,
                               const float* __restrict__ w0,
                               const float* __restrict__ w123,
                               const float* __restrict__ w4567,
                               const float* __restrict__ w8,
                               const float* __restrict__ wm,
                               const float* __restrict__ wg) {
    const int tid = threadIdx.x;
    if (blockIdx.x < NFRAMES) {
        __shared__ float xin[256];
        __shared__ float w0s[896];
        const int f = blockIdx.x;
        const int b = f >> 8, t = (f & 255) + 256;
        xin[tid] = x[(b * 256 + tid) * 512 + t];
        for (int i = tid; i < 896; i += 256) w0s[i] = w0[i];
        __syncthreads();
        const int co = tid & 127;
        const int ph = tid >> 7;
#pragma unroll 4
        for (int u = 0; u < 64; u++) {
            int p = ph * 64 + u;
            float s = 0.f;
#pragma unroll
            for (int k = 0; k < 7; k++) {
                int ip = 2 * p + k - 3;
                float xv = (ip >= 0 && ip < 256) ? xin[ip] : 0.f;
                s = fmaf(w0s[co * 7 + k], xv, s);
            }
            s = s > 0.f ? s : 0.2f * s;
            size_t o = ((size_t)f * 128 + p) * 128 + co;
            split1(s, g_pAhi[o], g_pAlo[o]);
        }
        PDL_TRIGGER();
        return;
    }
    const int stride = 512 * 256;
    const int t0 = (blockIdx.x - NFRAMES) * 256 + tid;
    for (int e = t0; e < 3 * 128 * 896; e += stride) {
        int l = e / (128 * 896), r = e % (128 * 896);
        int co = r / 896, k = r % 896;
        int kw = k >> 7, ci = k & 127;
        split1(w123[((l * 128 + co) * 128 + ci) * 7 + kw], g_w123hi[e], g_w123lo[e]);
    }
    for (int e = t0; e < 4 * 128 * 384; e += stride) {
        int l = e / (128 * 384), r = e % (128 * 384);
        int co = r / 384, k = r % 384;
        int kw = k >> 7, ci = k & 127;
        split1(w4567[((l * 128 + co) * 128 + ci) * 3 + kw], g_w4567hi[e], g_w4567lo[e]);
    }
    for (int e = t0; e < 256 * 128; e += stride) {
        int co = e >> 7, ci = e & 127;
        split1(w8[co * 128 + ci], g_w8hi[e], g_w8lo[e]);
    }
    for (int e = t0; e < 8 * 2 * 256 * 512; e += stride) {
        int lz = e / (256 * 512), r = e % (256 * 512);
        int co = r / 512, k = r % 512;
        int tap = k >> 8, ci = k & 255;
        int l = lz >> 1, z = lz & 1;
        const float* w = z ? wg : wm;
        split1(w[((l * 256 + co) * 256 + ci) * 2 + tap], g_wnhi[e], g_wnlo[e]);
    }
    PDL_TRIGGER();
}

// ---------------- conv-as-GEMM: 128x64, single-sync 2-stage pipeline --------
template <int KW, int PAD, int LIN, int LOUT, bool RELU, bool LAST>
__global__ __launch_bounds__(256, 2)
void conv_mma2(const __nv_bfloat16* __restrict__ in_hi,
               const __nv_bfloat16* __restrict__ in_lo,
               const __nv_bfloat16* __restrict__ w_hi,
               const __nv_bfloat16* __restrict__ w_lo,
               __nv_bfloat16* __restrict__ out_hi,
               __nv_bfloat16* __restrict__ out_lo) {
    constexpr int K = KW * 128;
    constexpr int NST = K / 64;
    constexpr int LOG = ILog2<LOUT>::v;
    extern __shared__ __align__(1024) char smem[];
    const uint32_t sb = smem_u32(smem);

    const int tid = threadIdx.x;
    const int lane = tid & 31;
    const int warp = tid >> 5;
    const int wm = (warp >> 1) * 32;
    const int wn_ = (warp & 1) * 32;
    const int col0 = blockIdx.x * 64;
    const int m0 = blockIdx.y * 128;

    float c[2][4][4];
#pragma unroll
    for (int i = 0; i < 2; i++)
#pragma unroll
        for (int j = 0; j < 4; j++)
#pragma unroll
            for (int k = 0; k < 4; k++) c[i][j][k] = 0.f;

    auto issue = [&](int s) {
        const uint32_t bo = sb + (s & 1) * BUFSZ;
        const int kw = s >> 1;
        const int ci0 = (s & 1) * 64;
#pragma unroll
        for (int g = 0; g < 4; g++) {
            int gi = tid + g * 256;
            int row = gi >> 3, j = gi & 7;
            uint32_t off = row * 128 + ((j ^ (row & 7)) << 4);
            size_t so = (size_t)(m0 + row) * K + s * 64 + j * 8;
            cp16(bo + SM_A_HI + off, w_hi + so, 16);
            cp16(bo + SM_A_LO + off, w_lo + so, 16);
        }
#pragma unroll
        for (int g = 0; g < 2; g++) {
            int gi = tid + g * 256;
            int row = gi >> 3, j = gi & 7;
            int col = col0 + row;
            int f = col >> LOG;
            int p = col & (LOUT - 1);
            int ip = 2 * p + kw - PAD;
            bool v = ((unsigned)ip < (unsigned)LIN);
            size_t so = ((size_t)f * LIN + (v ? ip : 0)) * 128 + ci0 + j * 8;
            int sz = v ? 16 : 0;
            uint32_t off = row * 128 + ((j ^ (row & 7)) << 4);
            cp16(bo + SM_B_HI + off, in_hi + so, sz);
            cp16(bo + SM_B_LO + off, in_lo + so, sz);
        }
    };

    PDL_WAIT();                       // upstream data (in_* and weights) ready
    issue(0); CP_COMMIT();
    for (int s = 0; s < NST; s++) {
        CP_WAIT(0);
        __syncthreads();
        const uint32_t base = sb + (s & 1) * BUFSZ;
        compute_kc(base, lane, wm, wn_, 0, c);
        if (s + 1 < NST) { issue(s + 1); CP_COMMIT(); }
        compute_kc(base, lane, wm, wn_, 16, c);
        compute_kc(base, lane, wm, wn_, 32, c);
        compute_kc(base, lane, wm, wn_, 48, c);
    }
    PDL_TRIGGER();                    // let dependent launch during epilogue

#pragma unroll
    for (int mi = 0; mi < 2; mi++) {
#pragma unroll
        for (int ni = 0; ni < 4; ni++) {
            int r0 = wm + mi * 16 + (lane >> 2);
            int colb = col0 + wn_ + ni * 8 + (lane & 3) * 2;
#pragma unroll
            for (int e = 0; e < 4; e++) {
                int row = r0 + (e >> 1) * 8;
                int col = colb + (e & 1);
                float xv = c[mi][ni][e];
                if (RELU) xv = xv > 0.f ? xv : 0.2f * xv;
                if (LAST) {
                    size_t o = (size_t)col * 256 + m0 + row;
                    g_H[0][o] = xv;
                    split1(xv, g_Hhi[0][o], g_Hlo[0][o]);
                    if ((col & 255) == 255)
                        g_Henc[(col >> 8) * 256 + m0 + row] = xv;
                } else {
                    size_t o = (size_t)col * 128 + row;
                    split1(xv, out_hi[o], out_lo[o]);
                }
            }
        }
    }
}

// ---------------- WaveNet GEMM (main+gate), sparse cone columns -------------
__global__ __launch_bounds__(256, 2)
void wn_mma2(int layer, int ncols) {
    extern __shared__ __align__(1024) char smem[];
    const uint32_t sb = smem_u32(smem);

    const int tid = threadIdx.x;
    const int lane = tid & 31;
    const int warp = tid >> 5;
    const int wm = (warp >> 1) * 32;
    const int wn_ = (warp & 1) * 32;
    const int col0 = blockIdx.x * 64;
    const int z = blockIdx.y >> 1;
    const int mh = blockIdx.y & 1;
    const int rd = layer & 1;
    const int dil = 1 << layer;
    const int ls = layer + 1;
    const int lperb = 7 - layer;
    const __nv_bfloat16* w_hi = g_wnhi + ((size_t)(layer * 2 + z) * 256 + mh * 128) * 512;
    const __nv_bfloat16* w_lo = g_wnlo + ((size_t)(layer * 2 + z) * 256 + mh * 128) * 512;
    const __nv_bfloat16* Hhi = g_Hhi[rd];
    const __nv_bfloat16* Hlo = g_Hlo[rd];

    float c[2][4][4];
#pragma unroll
    for (int i = 0; i < 2; i++)
#pragma unroll
        for (int j = 0; j < 4; j++)
#pragma unroll
            for (int k = 0; k < 4; k++) c[i][j][k] = 0.f;

    auto issue = [&](int s) {
        const uint32_t bo = sb + (s & 1) * BUFSZ;
        const int tap = s >> 2;
        const int ci0 = (s & 3) * 64;
#pragma unroll
        for (int g = 0; g < 4; g++) {
            int gi = tid + g * 256;
            int row = gi >> 3, j = gi & 7;
            uint32_t off = row * 128 + ((j ^ (row & 7)) << 4);
            size_t so = (size_t)row * 512 + s * 64 + j * 8;
            cp16(bo + SM_A_HI + off, w_hi + so, 16);
            cp16(bo + SM_A_LO + off, w_lo + so, 16);
        }
#pragma unroll
        for (int g = 0; g < 2; g++) {
            int gi = tid + g * 256;
            int row = gi >> 3, j = gi & 7;
            int colc = col0 + row;
            bool valid = colc < ncols;
            int cc = valid ? colc : 0;
            int b = cc >> lperb;
            int j2 = cc & ((1 << lperb) - 1);
            int tt = (j2 << ls) + (1 << ls) - 1;
            int scol = b * 256 + tt - (tap ? 0 : dil);
            size_t so = (size_t)scol * 256 + ci0 + j * 8;
            int sz = valid ? 16 : 0;
            uint32_t off = row * 128 + ((j ^ (row & 7)) << 4);
            cp16(bo + SM_B_HI + off, Hhi + so, sz);
            cp16(bo + SM_B_LO + off, Hlo + so, sz);
        }
    };

    PDL_WAIT();
    issue(0); CP_COMMIT();
    for (int s = 0; s < 8; s++) {
        CP_WAIT(0);
        __syncthreads();
        const uint32_t base = sb + (s & 1) * BUFSZ;
        compute_kc(base, lane, wm, wn_, 0, c);
        if (s + 1 < 8) { issue(s + 1); CP_COMMIT(); }
        compute_kc(base, lane, wm, wn_, 16, c);
        compute_kc(base, lane, wm, wn_, 32, c);
        compute_kc(base, lane, wm, wn_, 48, c);
    }
    PDL_TRIGGER();

    float* pre = g_pre + (size_t)z * 1024 * 256;
#pragma unroll
    for (int mi = 0; mi < 2; mi++) {
#pragma unroll
        for (int ni = 0; ni < 4; ni++) {
            int r0 = mh * 128 + wm + mi * 16 + (lane >> 2);
            int colb = col0 + wn_ + ni * 8 + (lane & 3) * 2;
#pragma unroll
            for (int e = 0; e < 4; e++) {
                int row = r0 + (e >> 1) * 8;
                int col = colb + (e & 1);
                if (col < ncols) pre[(size_t)col * 256 + row] = c[mi][ni][e];
            }
        }
    }
}

// ---------------- WaveNet pointwise: sparse cols, ping-pong H ----------------
__global__ void wn_pointwise(int layer) {
    PDL_WAIT();
    const int col = blockIdx.x;
    const int co = threadIdx.x;
    const int rd = layer & 1;
    const int ls = layer + 1;
    const int lperb = 7 - layer;
    int b = col >> lperb;
    int j2 = col & ((1 << lperb) - 1);
    int tt = (j2 << ls) + (1 << ls) - 1;
    size_t gidx = ((size_t)(b * 256 + tt)) * 256 + co;
    size_t pidx = (size_t)col * 256 + co;
    float pm = g_pre[pidx];
    float pg = g_pre[(size_t)1024 * 256 + pidx];
    float zv = tanhf(pm) * (1.f / (1.f + expf(-pg)));
    float h = g_H[rd][gidx] + zv;
    g_H[rd ^ 1][gidx] = h;
    split1(h, g_Hhi[rd ^ 1][gidx], g_Hlo[rd ^ 1][gidx]);
    PDL_TRIGGER();
}

// ---------------- finalize ---------------------------------------------------
__global__ void finalize_kernel(const float* __restrict__ jw,
                                float* __restrict__ out, int out_size) {
    PDL_WAIT();
    __shared__ float red[256];
    const int b = blockIdx.x;
    const int t = threadIdx.x;
    float v = g_H[0][((size_t)b * 256 + 255) * 256 + t] - g_Henc[b * 256 + t];
    out[b * 256 + t] = v;
    red[t] = v * jw[t];
    __syncthreads();
#pragma unroll
    for (int s = 128; s > 0; s >>= 1) {
        if (t < s) red[t] += red[t + s];
        __syncthreads();
    }
    if (t == 0 && out_size >= 2048 + 8) out[2048 + b] = red[0];
}

// ---------------- PDL launch helper ------------------------------------------
#define LAUNCH_PDL(kern, grid, block, smem, ...) do {                         \
    cudaLaunchConfig_t cfg_ = {};                                             \
    cfg_.gridDim = grid; cfg_.blockDim = block;                               \
    cfg_.dynamicSmemBytes = smem; cfg_.stream = 0;                            \
    cudaLaunchAttribute attr_[1];                                             \
    attr_[0].id = cudaLaunchAttributeProgrammaticStreamSerialization;         \
    attr_[0].val.programmaticStreamSerializationAllowed = 1;                  \
    cfg_.attrs = attr_; cfg_.numAttrs = 1;                                    \
    cudaLaunchKernelEx(&cfg_, kern, __VA_ARGS__);                             \
} while (0)

// ---------------- launch -----------------------------------------------------
extern "C" void kernel_launch(void* const* d_in, const int* in_sizes, int n_in,
                              void* d_out, int out_size) {
    const float* x     = (const float*)d_in[0];
    const float* w0    = (const float*)d_in[1];
    const float* w123  = (const float*)d_in[2];
    const float* w4567 = (const float*)d_in[3];
    const float* w8    = (const float*)d_in[4];
    const float* wm    = (const float*)d_in[5];
    const float* wg    = (const float*)d_in[6];
    const float* jw    = (const float*)d_in[7];
    float* out = (float*)d_out;

    __nv_bfloat16 *pAhi, *pAlo, *pBhi, *pBlo;
    __nv_bfloat16 *w123hi, *w123lo, *w4567hi, *w4567lo, *w8hi, *w8lo;
    cudaGetSymbolAddress((void**)&pAhi, g_pAhi);
    cudaGetSymbolAddress((void**)&pAlo, g_pAlo);
    cudaGetSymbolAddress((void**)&pBhi, g_pBhi);
    cudaGetSymbolAddress((void**)&pBlo, g_pBlo);
    cudaGetSymbolAddress((void**)&w123hi, g_w123hi);
    cudaGetSymbolAddress((void**)&w123lo, g_w123lo);
    cudaGetSymbolAddress((void**)&w4567hi, g_w4567hi);
    cudaGetSymbolAddress((void**)&w4567lo, g_w4567lo);
    cudaGetSymbolAddress((void**)&w8hi, g_w8hi);
    cudaGetSymbolAddress((void**)&w8lo, g_w8lo);

    cudaFuncSetAttribute(conv_mma2<7,3,128,64,true ,false>, cudaFuncAttributeMaxDynamicSharedMemorySize, SMEM_PIPE);
    cudaFuncSetAttribute(conv_mma2<7,3, 64,32,true ,false>, cudaFuncAttributeMaxDynamicSharedMemorySize, SMEM_PIPE);
    cudaFuncSetAttribute(conv_mma2<7,3, 32,16,true ,false>, cudaFuncAttributeMaxDynamicSharedMemorySize, SMEM_PIPE);
    cudaFuncSetAttribute(conv_mma2<3,1, 16, 8,true ,false>, cudaFuncAttributeMaxDynamicSharedMemorySize, SMEM_PIPE);
    cudaFuncSetAttribute(conv_mma2<3,1,  8, 4,true ,false>, cudaFuncAttributeMaxDynamicSharedMemorySize, SMEM_PIPE);
    cudaFuncSetAttribute(conv_mma2<3,1,  4, 2,true ,false>, cudaFuncAttributeMaxDynamicSharedMemorySize, SMEM_PIPE);
    cudaFuncSetAttribute(conv_mma2<3,1,  2, 1,true ,false>, cudaFuncAttributeMaxDynamicSharedMemorySize, SMEM_PIPE);
    cudaFuncSetAttribute(conv_mma2<1,0,  1, 1,false,true >, cudaFuncAttributeMaxDynamicSharedMemorySize, SMEM_PIPE);
    cudaFuncSetAttribute(wn_mma2, cudaFuncAttributeMaxDynamicSharedMemorySize, SMEM_PIPE);

    prep_and_conv0<<<NFRAMES + 512, 256>>>(x, w0, w123, w4567, w8, wm, wg);

    LAUNCH_PDL((conv_mma2<7,3,128,64,true ,false>), dim3(2048,1), dim3(256), (size_t)SMEM_PIPE,
               (const __nv_bfloat16*)pAhi, (const __nv_bfloat16*)pAlo,
               (const __nv_bfloat16*)w123hi, (const __nv_bfloat16*)w123lo, pBhi, pBlo);
    LAUNCH_PDL((conv_mma2<7,3, 64,32,true ,false>), dim3(1024,1), dim3(256), (size_t)SMEM_PIPE,
               (const __nv_bfloat16*)pBhi, (const __nv_bfloat16*)pBlo,
               (const __nv_bfloat16*)(w123hi + 1*128*896), (const __nv_bfloat16*)(w123lo + 1*128*896), pAhi, pAlo);
    LAUNCH_PDL((conv_mma2<7,3, 32,16,true ,false>), dim3( 512,1), dim3(256), (size_t)SMEM_PIPE,
               (const __nv_bfloat16*)pAhi, (const __nv_bfloat16*)pAlo,
               (const __nv_bfloat16*)(w123hi + 2*128*896), (const __nv_bfloat16*)(w123lo + 2*128*896), pBhi, pBlo);
    LAUNCH_PDL((conv_mma2<3,1, 16, 8,true ,false>), dim3( 256,1), dim3(256), (size_t)SMEM_PIPE,
               (const __nv_bfloat16*)pBhi, (const __nv_bfloat16*)pBlo,
               (const __nv_bfloat16*)w4567hi, (const __nv_bfloat16*)w4567lo, pAhi, pAlo);
    LAUNCH_PDL((conv_mma2<3,1,  8, 4,true ,false>), dim3( 128,1), dim3(256), (size_t)SMEM_PIPE,
               (const __nv_bfloat16*)pAhi, (const __nv_bfloat16*)pAlo,
               (const __nv_bfloat16*)(w4567hi + 1*128*384), (const __nv_bfloat16*)(w4567lo + 1*128*384), pBhi, pBlo);
    LAUNCH_PDL((conv_mma2<3,1,  4, 2,true ,false>), dim3(  64,1), dim3(256), (size_t)SMEM_PIPE,
               (const __nv_bfloat16*)pBhi, (const __nv_bfloat16*)pBlo,
               (const __nv_bfloat16*)(w4567hi + 2*128*384), (const __nv_bfloat16*)(w4567lo + 2*128*384), pAhi, pAlo);
    LAUNCH_PDL((conv_mma2<3,1,  2, 1,true ,false>), dim3(  32,1), dim3(256), (size_t)SMEM_PIPE,
               (const __nv_bfloat16*)pAhi, (const __nv_bfloat16*)pAlo,
               (const __nv_bfloat16*)(w4567hi + 3*128*384), (const __nv_bfloat16*)(w4567lo + 3*128*384), pBhi, pBlo);
    LAUNCH_PDL((conv_mma2<1,0,  1, 1,false,true >), dim3(  32,2), dim3(256), (size_t)SMEM_PIPE,
               (const __nv_bfloat16*)pBhi, (const __nv_bfloat16*)pBlo,
               (const __nv_bfloat16*)w8hi, (const __nv_bfloat16*)w8lo, pAhi, pAlo);

    for (int l = 0; l < 8; l++) {
        int ncols = 8 * (256 >> (l + 1));            // 1024, 512, ..., 8
        int gx = (ncols + 63) / 64;
        LAUNCH_PDL(wn_mma2, dim3(gx, 4), dim3(256), (size_t)SMEM_PIPE, l, ncols);
        LAUNCH_PDL(wn_pointwise, dim3(ncols), dim3(256), (size_t)0, l);
    }

    LAUNCH_PDL(finalize_kernel, dim3(8), dim3(256), (size_t)0,
               (const float*)jw, out, out_size);
}